// round 8
// baseline (speedup 1.0000x reference)
#include <cuda_runtime.h>
#include <cstdint>
#include <cstddef>

// ============================ problem constants ============================
#define BATCH_N   4096
#define KDIM      512
#define CLS       50000
#define CLSP      50048              // padded to 391*128
#define SCALE_F   30.0f
#define LMAX_F    30.0f
#define COSM_F    0.8775825618903728f
#define SINM_F    0.479425538604203f
#define TH_F     (-0.8775825618903728f)
#define MMV_F     0.23971276930210156f

// ============================ device scratch ===============================
__device__ float g_Xr[BATCH_N * KDIM];   // tf32-rounded, k-permuted X
__device__ float g_Wr[CLSP * KDIM];      // tf32-rounded, k-permuted W (padded)
__device__ float g_invx[BATCH_N];
__device__ float g_invw[CLSP];
__device__ int   g_label[BATCH_N];
__device__ float g_rowsum[BATCH_N];      // sum of exp(logit - 30) per row
__device__ float g_tgt[BATCH_N];         // target-class logit per row
__device__ unsigned int g_ctr = 0;       // CTA completion counter

// ============================ helpers ======================================
__device__ __forceinline__ float f2tf32(float f) {
    uint32_t r; asm("cvt.rna.tf32.f32 %0, %1;" : "=r"(r) : "f"(f));
    return __uint_as_float(r);
}

#define MMA_TF32(c, A0, A1, A2, A3, B0, B1) \
    asm volatile("mma.sync.aligned.m16n8k8.row.col.f32.tf32.tf32.f32 " \
        "{%0,%1,%2,%3}, {%4,%5,%6,%7}, {%8,%9}, {%0,%1,%2,%3};" \
        : "+f"((c)[0]), "+f"((c)[1]), "+f"((c)[2]), "+f"((c)[3]) \
        : "r"(__float_as_uint(A0)), "r"(__float_as_uint(A1)), \
          "r"(__float_as_uint(A2)), "r"(__float_as_uint(A3)), \
          "r"(__float_as_uint(B0)), "r"(__float_as_uint(B1)))

#define CP16(dst_u32, src_gptr) \
    asm volatile("cp.async.cg.shared.global [%0], [%1], 16;" \
        :: "r"(dst_u32), "l"(src_gptr) : "memory")
#define CP_COMMIT() asm volatile("cp.async.commit_group;" ::: "memory")
#define CP_WAIT(n)  asm volatile("cp.async.wait_group %0;" :: "n"(n) : "memory")

__device__ __forceinline__ uint32_t smem_u32(const void* p) {
    uint32_t a;
    asm("{ .reg .u64 t; cvta.to.shared.u64 t, %1; cvt.u32.u64 %0, t; }" : "=r"(a) : "l"(p));
    return a;
}

// ============================ GEMM config ==================================
#define BM     256
#define BN     128
#define BK     16
#define NCH    (KDIM / BK)            // 32
#define STAGES 4
#define SST    20                     // smem row stride (floats), pad 4
#define STAGEF ((BM + BN) * SST)      // 7680 floats per stage
#define DSMEM_BYTES (STAGES * STAGEF * 4)   // 122880 B
#define NTHREADS 512

__device__ __forceinline__ float arc_apply(float cosv, bool istgt) {
    float o = cosv;
    if (istgt) {
        float sine = sqrtf(fmaxf(0.0f, 1.0f - cosv * cosv));
        float phi = cosv * COSM_F - sine * SINM_F;
        o = (cosv > TH_F) ? phi : (cosv - MMV_F);
    }
    return o * SCALE_F;
}

// ============================ prep kernel ==================================
// blocks 0..4095:      X rows -> norm + tf32-round + k-permute into g_Xr
// blocks 4096..54143:  W rows -> same into g_Wr (rows >= CLS zero-padded)
// block  54144:        labels (int64/int32 detect + convert) + zero g_rowsum
// k-permutation within each 16-float group: element p -> pos (p&3)*4 + (p>>2)
__global__ void __launch_bounds__(128) prep_kernel(
    const float* __restrict__ X, const float* __restrict__ W,
    const int* __restrict__ L)
{
    const int b = blockIdx.x;
    const int t = threadIdx.x;

    if (b < BATCH_N + CLSP) {
        const bool isX = (b < BATCH_N);
        const int row = isX ? b : (b - BATCH_N);
        const float* src = isX ? (X + (size_t)row * KDIM)
                               : (W + (size_t)row * KDIM);
        float* dst = isX ? (g_Xr + (size_t)row * KDIM)
                         : (g_Wr + (size_t)row * KDIM);
        const bool valid = isX || (row < CLS);

        float4 v = make_float4(0.f, 0.f, 0.f, 0.f);
        if (valid) v = *(const float4*)(src + t * 4);
        float ss = v.x * v.x + v.y * v.y + v.z * v.z + v.w * v.w;

        float* gdst = dst + (t >> 2) * 16 + (t & 3);
        gdst[0]  = f2tf32(v.x);
        gdst[4]  = f2tf32(v.y);
        gdst[8]  = f2tf32(v.z);
        gdst[12] = f2tf32(v.w);

        #pragma unroll
        for (int o = 16; o; o >>= 1) ss += __shfl_down_sync(0xffffffffu, ss, o);
        __shared__ float ws[4];
        if ((t & 31) == 0) ws[t >> 5] = ss;
        __syncthreads();
        if (t == 0) {
            float tot = ws[0] + ws[1] + ws[2] + ws[3];
            float inv = valid ? (1.0f / fmaxf(sqrtf(tot), 1e-12f)) : 1.0f;
            if (isX) g_invx[row] = inv; else g_invw[row] = inv;
        }
    } else {
        int nz = 0;
        for (int i = t; i < 2048; i += 128)
            if (L[2 * i + 1] != 0) nz = 1;
        int any = __syncthreads_or(nz);
        const int is64 = any ? 0 : 1;
        for (int i = t; i < BATCH_N; i += 128) {
            g_label[i] = is64 ? L[2 * i] : L[i];
            g_rowsum[i] = 0.0f;
        }
    }
}

// ============================ main GEMM + ArcFace + loss ===================
extern __shared__ float smf[];

__device__ __forceinline__ void compute_chunk(
    const float* __restrict__ sb, int wm, int wn, int g, int tm,
    float acc[4][4][4])
{
    const float* Ab = sb + (wm * 64 + g) * SST + 4 * tm;
    const float* Bb = sb + (BM + wn * 32 + g) * SST + 4 * tm;
    float4 bq0 = *(const float4*)(Bb);
    float4 bq1 = *(const float4*)(Bb + 8  * SST);
    float4 bq2 = *(const float4*)(Bb + 16 * SST);
    float4 bq3 = *(const float4*)(Bb + 24 * SST);
    #pragma unroll
    for (int i = 0; i < 4; ++i) {
        float4 alo = *(const float4*)(Ab + (i * 16)     * SST);
        float4 ahi = *(const float4*)(Ab + (i * 16 + 8) * SST);
        MMA_TF32(acc[i][0], alo.x, ahi.x, alo.y, ahi.y, bq0.x, bq0.y);
        MMA_TF32(acc[i][1], alo.x, ahi.x, alo.y, ahi.y, bq1.x, bq1.y);
        MMA_TF32(acc[i][2], alo.x, ahi.x, alo.y, ahi.y, bq2.x, bq2.y);
        MMA_TF32(acc[i][3], alo.x, ahi.x, alo.y, ahi.y, bq3.x, bq3.y);
        MMA_TF32(acc[i][0], alo.z, ahi.z, alo.w, ahi.w, bq0.z, bq0.w);
        MMA_TF32(acc[i][1], alo.z, ahi.z, alo.w, ahi.w, bq1.z, bq1.w);
        MMA_TF32(acc[i][2], alo.z, ahi.z, alo.w, ahi.w, bq2.z, bq2.w);
        MMA_TF32(acc[i][3], alo.z, ahi.z, alo.w, ahi.w, bq3.z, bq3.w);
    }
}

__global__ void __launch_bounds__(NTHREADS, 1)
gemm_arcface_kernel(float* __restrict__ out, int do_loss)
{
    const int tid  = threadIdx.x;
    const int lane = tid & 31;
    const int wid  = tid >> 5;          // 0..15
    const int g    = lane >> 2;
    const int tm   = lane & 3;
    const int wm   = wid & 3;           // warp M index 0..3 (64 rows each)
    const int wn   = wid >> 2;          // warp N index 0..3 (32 cols each)
    const int rowBase = blockIdx.x * BM;
    const int colBase = blockIdx.y * BN;

    const uint32_t sbase = smem_u32(smf);

    // cp.async mapping: A covers 256 rows (ids tid, tid+512), B covers 128 rows
    const int r0c = tid >> 2, lc = tid & 3;
    const int r1c = r0c + 128;
    const float* xsrc0 = g_Xr + (size_t)(rowBase + r0c) * KDIM + lc * 4;
    const float* xsrc1 = g_Xr + (size_t)(rowBase + r1c) * KDIM + lc * 4;
    const float* wsrc0 = g_Wr + (size_t)(colBase + r0c) * KDIM + lc * 4;
    const uint32_t dA0 = sbase + (r0c * SST + lc * 4) * 4;
    const uint32_t dA1 = sbase + (r1c * SST + lc * 4) * 4;
    const uint32_t dB0 = sbase + ((BM + r0c) * SST + lc * 4) * 4;

    float acc[4][4][4];
    #pragma unroll
    for (int i = 0; i < 4; ++i)
        #pragma unroll
        for (int j = 0; j < 4; ++j)
            #pragma unroll
            for (int q = 0; q < 4; ++q) acc[i][j][q] = 0.f;

    // prologue: stages 0..STAGES-2
    #pragma unroll
    for (int s = 0; s < STAGES - 1; ++s) {
        const uint32_t so = (uint32_t)(s * STAGEF * 4);
        const int ko = s * BK;
        CP16(dA0 + so, xsrc0 + ko);
        CP16(dA1 + so, xsrc1 + ko);
        CP16(dB0 + so, wsrc0 + ko);
        CP_COMMIT();
    }

    #pragma unroll 2
    for (int c = 0; c < NCH - 2; ++c) {
        CP_WAIT(2);
        __syncthreads();
        if (c + STAGES - 1 < NCH) {
            const int s = (c + STAGES - 1) & (STAGES - 1);
            const uint32_t so = (uint32_t)(s * STAGEF * 4);
            const int ko = (c + STAGES - 1) * BK;
            CP16(dA0 + so, xsrc0 + ko);
            CP16(dA1 + so, xsrc1 + ko);
            CP16(dB0 + so, wsrc0 + ko);
            CP_COMMIT();
        }
        compute_chunk(smf + (c & (STAGES - 1)) * STAGEF, wm, wn, g, tm, acc);
    }
    CP_WAIT(1);
    __syncthreads();
    compute_chunk(smf + ((NCH - 2) & (STAGES - 1)) * STAGEF, wm, wn, g, tm, acc);
    CP_WAIT(0);
    __syncthreads();
    compute_chunk(smf + ((NCH - 1) & (STAGES - 1)) * STAGEF, wm, wn, g, tm, acc);

    // ---- epilogue: normalize, ArcFace margin, scale, store, fused LSE ----
    __syncthreads();
    float* rowacc = smf;               // reuse stage smem: 256 floats
    if (tid < BM) rowacc[tid] = 0.f;
    __syncthreads();

    const int wrowb = rowBase + wm * 64;
    const int wcolb = colBase + wn * 32;
    #pragma unroll
    for (int i = 0; i < 4; ++i) {
        const int r0 = wrowb + i * 16 + g;
        const int r1 = r0 + 8;
        const float ix0 = g_invx[r0], ix1 = g_invx[r1];
        const int lab0 = g_label[r0], lab1 = g_label[r1];
        float* o0 = out + (size_t)r0 * CLS;
        float* o1 = out + (size_t)r1 * CLS;
        float es0 = 0.f, es1 = 0.f;
        #pragma unroll
        for (int j = 0; j < 4; ++j) {
            const int cc = wcolb + j * 8 + 2 * tm;
            if (cc < CLS) {   // cc even, CLS even => cc+1 < CLS too
                const float iw0 = g_invw[cc], iw1 = g_invw[cc + 1];
                const bool t00 = (cc == lab0), t01 = (cc + 1 == lab0);
                const bool t10 = (cc == lab1), t11 = (cc + 1 == lab1);
                float2 v0, v1;
                v0.x = arc_apply(acc[i][j][0] * ix0 * iw0, t00);
                v0.y = arc_apply(acc[i][j][1] * ix0 * iw1, t01);
                v1.x = arc_apply(acc[i][j][2] * ix1 * iw0, t10);
                v1.y = arc_apply(acc[i][j][3] * ix1 * iw1, t11);
                *(float2*)(o0 + cc) = v0;
                *(float2*)(o1 + cc) = v1;
                es0 += __expf(v0.x - LMAX_F) + __expf(v0.y - LMAX_F);
                es1 += __expf(v1.x - LMAX_F) + __expf(v1.y - LMAX_F);
                if (t00) g_tgt[r0] = v0.x;
                if (t01) g_tgt[r0] = v0.y;
                if (t10) g_tgt[r1] = v1.x;
                if (t11) g_tgt[r1] = v1.y;
            }
        }
        es0 += __shfl_xor_sync(0xffffffffu, es0, 1);
        es0 += __shfl_xor_sync(0xffffffffu, es0, 2);
        es1 += __shfl_xor_sync(0xffffffffu, es1, 1);
        es1 += __shfl_xor_sync(0xffffffffu, es1, 2);
        if (tm == 0) {
            atomicAdd(&rowacc[wm * 64 + i * 16 + g],     es0);
            atomicAdd(&rowacc[wm * 64 + i * 16 + g + 8], es1);
        }
    }
    __syncthreads();
    if (tid < BM) atomicAdd(&g_rowsum[rowBase + tid], rowacc[tid]);

    // ---- completion-counter: last CTA computes the CE loss ----
    __shared__ unsigned int s_last;
    __syncthreads();                    // all g_rowsum atomics issued
    if (tid == 0) {
        __threadfence();
        unsigned int total = gridDim.x * gridDim.y;
        unsigned int old = atomicAdd(&g_ctr, 1u);
        s_last = (old == total - 1u) ? 1u : 0u;
    }
    __syncthreads();
    if (s_last) {
        if (tid == 0) g_ctr = 0;        // reset for next call
        if (do_loss) {
            __threadfence();
            float s = 0.f;
            for (int i = tid; i < BATCH_N; i += NTHREADS)
                s += (LMAX_F + logf(g_rowsum[i])) - g_tgt[i];
            #pragma unroll
            for (int o = 16; o; o >>= 1) s += __shfl_down_sync(0xffffffffu, s, o);
            float* lsm = smf + 512;     // scratch (stage area, free now)
            if (lane == 0) lsm[wid] = s;
            __syncthreads();
            if (tid == 0) {
                float t = 0.f;
                #pragma unroll
                for (int w = 0; w < NTHREADS / 32; ++w) t += lsm[w];
                out[(size_t)BATCH_N * CLS] = t * (1.0f / (float)BATCH_N);
            }
        }
    }
}

// ============================ launcher =====================================
extern "C" void kernel_launch(void* const* d_in, const int* in_sizes, int n_in,
                              void* d_out, int out_size) {
    const float* X = nullptr;
    const float* W = nullptr;
    const int*   L = nullptr;
    for (int i = 0; i < n_in; ++i) {
        if (in_sizes[i] == BATCH_N * KDIM)      X = (const float*)d_in[i];
        else if (in_sizes[i] == CLS * KDIM)     W = (const float*)d_in[i];
        else if (in_sizes[i] == BATCH_N)        L = (const int*)d_in[i];
    }
    float* out = (float*)d_out;
    const int do_loss = ((long long)out_size > (long long)BATCH_N * CLS) ? 1 : 0;

    cudaFuncSetAttribute(gemm_arcface_kernel,
                         cudaFuncAttributeMaxDynamicSharedMemorySize, DSMEM_BYTES);

    // exactly 2 launches per call => ncu -s 5 lands on GEMM
    prep_kernel<<<BATCH_N + CLSP + 1, 128>>>(X, W, L);

    dim3 grid(BATCH_N / BM, CLSP / BN);    // x fast-varying: share W tile in L2
    gemm_arcface_kernel<<<grid, NTHREADS, DSMEM_BYTES>>>(out, do_loss);
}

// round 9
// speedup vs baseline: 1.1068x; 1.1068x over previous
#include <cuda_runtime.h>
#include <cstdint>
#include <cstddef>

// ============================ problem constants ============================
#define BATCH_N   4096
#define KDIM      512
#define CLS       50000
#define CLSP      50048              // padded to 391*128
#define SCALE_F   30.0f
#define LMAX_F    30.0f
#define COSM_F    0.8775825618903728f
#define SINM_F    0.479425538604203f
#define TH_F     (-0.8775825618903728f)
#define MMV_F     0.23971276930210156f

// ============================ device scratch ===============================
__device__ float g_Xr[BATCH_N * KDIM];   // tf32-rounded, k-permuted X
__device__ float g_Wr[CLSP * KDIM];      // tf32-rounded, k-permuted W (padded)
__device__ float g_invx[BATCH_N];
__device__ float g_invw[CLSP];
__device__ int   g_label[BATCH_N];
__device__ float g_rowsum[BATCH_N];      // sum of exp(logit - 30) per row
__device__ float g_tgt[BATCH_N];         // target-class logit per row
__device__ unsigned int g_ctr = 0;       // CTA completion counter

// ============================ helpers ======================================
__device__ __forceinline__ float f2tf32(float f) {
    uint32_t r; asm("cvt.rna.tf32.f32 %0, %1;" : "=r"(r) : "f"(f));
    return __uint_as_float(r);
}

#define MMA_TF32(c, A0, A1, A2, A3, B0, B1) \
    asm volatile("mma.sync.aligned.m16n8k8.row.col.f32.tf32.tf32.f32 " \
        "{%0,%1,%2,%3}, {%4,%5,%6,%7}, {%8,%9}, {%0,%1,%2,%3};" \
        : "+f"((c)[0]), "+f"((c)[1]), "+f"((c)[2]), "+f"((c)[3]) \
        : "r"(__float_as_uint(A0)), "r"(__float_as_uint(A1)), \
          "r"(__float_as_uint(A2)), "r"(__float_as_uint(A3)), \
          "r"(__float_as_uint(B0)), "r"(__float_as_uint(B1)))

#define CP16(dst_u32, src_gptr) \
    asm volatile("cp.async.cg.shared.global [%0], [%1], 16;" \
        :: "r"(dst_u32), "l"(src_gptr) : "memory")
#define CP_COMMIT() asm volatile("cp.async.commit_group;" ::: "memory")
#define CP_WAIT(n)  asm volatile("cp.async.wait_group %0;" :: "n"(n) : "memory")

__device__ __forceinline__ uint32_t smem_u32(const void* p) {
    uint32_t a;
    asm("{ .reg .u64 t; cvta.to.shared.u64 t, %1; cvt.u32.u64 %0, t; }" : "=r"(a) : "l"(p));
    return a;
}

// ============================ GEMM config ==================================
#define BM     128
#define BN     128
#define BK     16
#define NCH    (KDIM / BK)            // 32
#define STAGES 4
#define SST    20                     // smem row stride (floats), pad 4
#define STAGEF ((BM + BN) * SST)      // 5120 floats per stage
#define DSMEM_BYTES (STAGES * STAGEF * 4)   // 81920 B
#define NTHREADS 256

__device__ __forceinline__ float arc_apply(float cosv, bool istgt) {
    float o = cosv;
    if (istgt) {
        float sine = sqrtf(fmaxf(0.0f, 1.0f - cosv * cosv));
        float phi = cosv * COSM_F - sine * SINM_F;
        o = (cosv > TH_F) ? phi : (cosv - MMV_F);
    }
    return o * SCALE_F;
}

// ============================ prep kernel ==================================
// k-permutation within each 16-float group: element p -> pos (p&3)*4 + (p>>2)
__global__ void __launch_bounds__(128) prep_kernel(
    const float* __restrict__ X, const float* __restrict__ W,
    const int* __restrict__ L)
{
    const int b = blockIdx.x;
    const int t = threadIdx.x;

    if (b < BATCH_N + CLSP) {
        const bool isX = (b < BATCH_N);
        const int row = isX ? b : (b - BATCH_N);
        const float* src = isX ? (X + (size_t)row * KDIM)
                               : (W + (size_t)row * KDIM);
        float* dst = isX ? (g_Xr + (size_t)row * KDIM)
                         : (g_Wr + (size_t)row * KDIM);
        const bool valid = isX || (row < CLS);

        float4 v = make_float4(0.f, 0.f, 0.f, 0.f);
        if (valid) v = *(const float4*)(src + t * 4);
        float ss = v.x * v.x + v.y * v.y + v.z * v.z + v.w * v.w;

        float* gdst = dst + (t >> 2) * 16 + (t & 3);
        gdst[0]  = f2tf32(v.x);
        gdst[4]  = f2tf32(v.y);
        gdst[8]  = f2tf32(v.z);
        gdst[12] = f2tf32(v.w);

        #pragma unroll
        for (int o = 16; o; o >>= 1) ss += __shfl_down_sync(0xffffffffu, ss, o);
        __shared__ float ws[4];
        if ((t & 31) == 0) ws[t >> 5] = ss;
        __syncthreads();
        if (t == 0) {
            float tot = ws[0] + ws[1] + ws[2] + ws[3];
            float inv = valid ? (1.0f / fmaxf(sqrtf(tot), 1e-12f)) : 1.0f;
            if (isX) g_invx[row] = inv; else g_invw[row] = inv;
        }
    } else {
        int nz = 0;
        for (int i = t; i < 2048; i += 128)
            if (L[2 * i + 1] != 0) nz = 1;
        int any = __syncthreads_or(nz);
        const int is64 = any ? 0 : 1;
        for (int i = t; i < BATCH_N; i += 128) {
            g_label[i] = is64 ? L[2 * i] : L[i];
            g_rowsum[i] = 0.0f;
        }
    }
}

// ============================ main GEMM + ArcFace + loss ===================
extern __shared__ float smf[];

__device__ __forceinline__ void compute_chunk(
    const float* __restrict__ sb, int aoff, int boff,
    float acc[4][4][4])
{
    const float* Ab = sb + aoff;
    const float* Bb = sb + boff;
    float4 bq0 = *(const float4*)(Bb);
    float4 bq1 = *(const float4*)(Bb + 8  * SST);
    float4 bq2 = *(const float4*)(Bb + 16 * SST);
    float4 bq3 = *(const float4*)(Bb + 24 * SST);
    #pragma unroll
    for (int i = 0; i < 4; ++i) {
        float4 alo = *(const float4*)(Ab + (i * 16)     * SST);
        float4 ahi = *(const float4*)(Ab + (i * 16 + 8) * SST);
        MMA_TF32(acc[i][0], alo.x, ahi.x, alo.y, ahi.y, bq0.x, bq0.y);
        MMA_TF32(acc[i][1], alo.x, ahi.x, alo.y, ahi.y, bq1.x, bq1.y);
        MMA_TF32(acc[i][2], alo.x, ahi.x, alo.y, ahi.y, bq2.x, bq2.y);
        MMA_TF32(acc[i][3], alo.x, ahi.x, alo.y, ahi.y, bq3.x, bq3.y);
        MMA_TF32(acc[i][0], alo.z, ahi.z, alo.w, ahi.w, bq0.z, bq0.w);
        MMA_TF32(acc[i][1], alo.z, ahi.z, alo.w, ahi.w, bq1.z, bq1.w);
        MMA_TF32(acc[i][2], alo.z, ahi.z, alo.w, ahi.w, bq2.z, bq2.w);
        MMA_TF32(acc[i][3], alo.z, ahi.z, alo.w, ahi.w, bq3.z, bq3.w);
    }
}

__global__ void __launch_bounds__(NTHREADS, 2)
gemm_arcface_kernel(float* __restrict__ out, int do_loss)
{
    const int tid  = threadIdx.x;
    const int lane = tid & 31;
    const int wid  = tid >> 5;          // 0..7
    const int g    = lane >> 2;
    const int tm   = lane & 3;
    const int wm   = wid & 1;           // warp M index (0..1), 64 rows
    const int wn   = wid >> 1;          // warp N index (0..3), 32 cols
    const int rowBase = blockIdx.x * BM;
    const int colBase = blockIdx.y * BN;

    const uint32_t sbase = smem_u32(smf);

    // fragment smem offsets (floats), loop-invariant
    const int aoff = (wm * 64 + g) * SST + 4 * tm;
    const int boff = (BM + wn * 32 + g) * SST + 4 * tm;

    // cp.async mapping: thread covers rows (lr, lr+64) of both A and B
    const int r0c = tid >> 2, lc = tid & 3;
    const int r1c = r0c + 64;
    const float* xs0 = g_Xr + (size_t)(rowBase + r0c) * KDIM + lc * 4;
    const float* xs1 = g_Xr + (size_t)(rowBase + r1c) * KDIM + lc * 4;
    const float* ws0 = g_Wr + (size_t)(colBase + r0c) * KDIM + lc * 4;
    const float* ws1 = g_Wr + (size_t)(colBase + r1c) * KDIM + lc * 4;
    const uint32_t dA0 = sbase + (r0c * SST + lc * 4) * 4;
    const uint32_t dA1 = sbase + (r1c * SST + lc * 4) * 4;
    const uint32_t dB0 = sbase + ((BM + r0c) * SST + lc * 4) * 4;
    const uint32_t dB1 = sbase + ((BM + r1c) * SST + lc * 4) * 4;

    float acc[4][4][4];
    #pragma unroll
    for (int i = 0; i < 4; ++i)
        #pragma unroll
        for (int j = 0; j < 4; ++j)
            #pragma unroll
            for (int q = 0; q < 4; ++q) acc[i][j][q] = 0.f;

    // prologue: stages 0..2 = chunks 0..2
    #pragma unroll
    for (int s = 0; s < STAGES - 1; ++s) {
        const uint32_t so = (uint32_t)(s * STAGEF * 4);
        const int ko = s * BK;
        CP16(dA0 + so, xs0 + ko);
        CP16(dA1 + so, xs1 + ko);
        CP16(dB0 + so, ws0 + ko);
        CP16(dB1 + so, ws1 + ko);
        CP_COMMIT();
    }

    // main loop: 7 outer blocks of 4 fully-unrolled chunks (chunks 0..27)
    // all stage offsets are compile-time constants; global ptrs advance 64/blk
    #pragma unroll 1
    for (int cb = 0; cb < NCH / STAGES - 1; ++cb) {
        #pragma unroll
        for (int s = 0; s < STAGES; ++s) {
            CP_WAIT(2);
            __syncthreads();
            const uint32_t so = (uint32_t)((((s + 3) & 3) * STAGEF) * 4);
            const int ko = (s + 3) * BK;        // + cb*64 via pointer advance
            CP16(dA0 + so, xs0 + ko);
            CP16(dA1 + so, xs1 + ko);
            CP16(dB0 + so, ws0 + ko);
            CP16(dB1 + so, ws1 + ko);
            CP_COMMIT();
            compute_chunk(smf + s * STAGEF, aoff, boff, acc);
        }
        xs0 += STAGES * BK; xs1 += STAGES * BK;
        ws0 += STAGES * BK; ws1 += STAGES * BK;
    }
    // tail block: chunks 28..31 (prefetch only chunk 31)
    CP_WAIT(2);
    __syncthreads();
    {
        const uint32_t so = (uint32_t)(3 * STAGEF * 4);
        const int ko = 3 * BK;
        CP16(dA0 + so, xs0 + ko);
        CP16(dA1 + so, xs1 + ko);
        CP16(dB0 + so, ws0 + ko);
        CP16(dB1 + so, ws1 + ko);
        CP_COMMIT();
    }
    compute_chunk(smf + 0 * STAGEF, aoff, boff, acc);
    CP_WAIT(2);
    __syncthreads();
    compute_chunk(smf + 1 * STAGEF, aoff, boff, acc);
    CP_WAIT(1);
    __syncthreads();
    compute_chunk(smf + 2 * STAGEF, aoff, boff, acc);
    CP_WAIT(0);
    __syncthreads();
    compute_chunk(smf + 3 * STAGEF, aoff, boff, acc);

    // ---- epilogue: normalize, ArcFace margin, scale, store, fused LSE ----
    __syncthreads();
    float* rowacc = smf;               // reuse stage smem: 128 floats
    if (tid < BM) rowacc[tid] = 0.f;
    __syncthreads();

    const int wrowb = rowBase + wm * 64;
    const int wcolb = colBase + wn * 32;
    #pragma unroll
    for (int i = 0; i < 4; ++i) {
        const int r0 = wrowb + i * 16 + g;
        const int r1 = r0 + 8;
        const float ix0 = g_invx[r0], ix1 = g_invx[r1];
        const int lab0 = g_label[r0], lab1 = g_label[r1];
        float* o0 = out + (size_t)r0 * CLS;
        float* o1 = out + (size_t)r1 * CLS;
        float es0 = 0.f, es1 = 0.f;
        #pragma unroll
        for (int j = 0; j < 4; ++j) {
            const int cc = wcolb + j * 8 + 2 * tm;
            if (cc < CLS) {   // cc even, CLS even => cc+1 < CLS too
                const float iw0 = g_invw[cc], iw1 = g_invw[cc + 1];
                const bool t00 = (cc == lab0), t01 = (cc + 1 == lab0);
                const bool t10 = (cc == lab1), t11 = (cc + 1 == lab1);
                float2 v0, v1;
                v0.x = arc_apply(acc[i][j][0] * ix0 * iw0, t00);
                v0.y = arc_apply(acc[i][j][1] * ix0 * iw1, t01);
                v1.x = arc_apply(acc[i][j][2] * ix1 * iw0, t10);
                v1.y = arc_apply(acc[i][j][3] * ix1 * iw1, t11);
                *(float2*)(o0 + cc) = v0;
                *(float2*)(o1 + cc) = v1;
                es0 += __expf(v0.x - LMAX_F) + __expf(v0.y - LMAX_F);
                es1 += __expf(v1.x - LMAX_F) + __expf(v1.y - LMAX_F);
                if (t00) g_tgt[r0] = v0.x;
                if (t01) g_tgt[r0] = v0.y;
                if (t10) g_tgt[r1] = v1.x;
                if (t11) g_tgt[r1] = v1.y;
            }
        }
        es0 += __shfl_xor_sync(0xffffffffu, es0, 1);
        es0 += __shfl_xor_sync(0xffffffffu, es0, 2);
        es1 += __shfl_xor_sync(0xffffffffu, es1, 1);
        es1 += __shfl_xor_sync(0xffffffffu, es1, 2);
        if (tm == 0) {
            atomicAdd(&rowacc[wm * 64 + i * 16 + g],     es0);
            atomicAdd(&rowacc[wm * 64 + i * 16 + g + 8], es1);
        }
    }
    __syncthreads();
    if (tid < BM) atomicAdd(&g_rowsum[rowBase + tid], rowacc[tid]);

    // ---- completion-counter: last CTA computes the CE loss ----
    __shared__ unsigned int s_last;
    __syncthreads();
    if (tid == 0) {
        __threadfence();
        unsigned int total = gridDim.x * gridDim.y;
        unsigned int old = atomicAdd(&g_ctr, 1u);
        s_last = (old == total - 1u) ? 1u : 0u;
    }
    __syncthreads();
    if (s_last) {
        if (tid == 0) g_ctr = 0;
        if (do_loss) {
            __threadfence();
            float s = 0.f;
            for (int i = tid; i < BATCH_N; i += NTHREADS)
                s += (LMAX_F + logf(g_rowsum[i])) - g_tgt[i];
            #pragma unroll
            for (int o = 16; o; o >>= 1) s += __shfl_down_sync(0xffffffffu, s, o);
            float* lsm = smf + 256;
            if (lane == 0) lsm[wid] = s;
            __syncthreads();
            if (tid == 0) {
                float t = 0.f;
                #pragma unroll
                for (int w = 0; w < NTHREADS / 32; ++w) t += lsm[w];
                out[(size_t)BATCH_N * CLS] = t * (1.0f / (float)BATCH_N);
            }
        }
    }
}

// ============================ launcher =====================================
extern "C" void kernel_launch(void* const* d_in, const int* in_sizes, int n_in,
                              void* d_out, int out_size) {
    const float* X = nullptr;
    const float* W = nullptr;
    const int*   L = nullptr;
    for (int i = 0; i < n_in; ++i) {
        if (in_sizes[i] == BATCH_N * KDIM)      X = (const float*)d_in[i];
        else if (in_sizes[i] == CLS * KDIM)     W = (const float*)d_in[i];
        else if (in_sizes[i] == BATCH_N)        L = (const int*)d_in[i];
    }
    float* out = (float*)d_out;
    const int do_loss = ((long long)out_size > (long long)BATCH_N * CLS) ? 1 : 0;

    cudaFuncSetAttribute(gemm_arcface_kernel,
                         cudaFuncAttributeMaxDynamicSharedMemorySize, DSMEM_BYTES);

    // exactly 2 launches per call => ncu -s 5 lands on GEMM
    prep_kernel<<<BATCH_N + CLSP + 1, 128>>>(X, W, L);

    dim3 grid(BATCH_N / BM, CLSP / BN);    // x fast-varying: share W tile in L2
    gemm_arcface_kernel<<<grid, NTHREADS, DSMEM_BYTES>>>(out, do_loss);
}

// round 10
// speedup vs baseline: 1.1514x; 1.0403x over previous
#include <cuda_runtime.h>
#include <cstdint>
#include <cstddef>

// ============================ problem constants ============================
#define BATCH_N   4096
#define KDIM      512
#define CLS       50000
#define CLSP      50048              // padded to 391*128
#define SCALE_F   30.0f
#define LMAX_F    30.0f
#define COSM_F    0.8775825618903728f
#define SINM_F    0.479425538604203f
#define TH_F     (-0.8775825618903728f)
#define MMV_F     0.23971276930210156f

// ============================ device scratch ===============================
__device__ float g_Xr[BATCH_N * KDIM];   // tf32-rounded, k-permuted X
__device__ float g_Wr[CLSP * KDIM];      // tf32-rounded, k-permuted W (padded)
__device__ float g_invx[BATCH_N];
__device__ float g_invw[CLSP];
__device__ int   g_label[BATCH_N];
__device__ float g_rowsum[BATCH_N];      // sum of exp(logit - 30) per row
__device__ float g_tgt[BATCH_N];         // target-class logit per row
__device__ unsigned int g_ctr = 0;       // CTA completion counter

// ============================ helpers ======================================
__device__ __forceinline__ float f2tf32(float f) {
    uint32_t r; asm("cvt.rna.tf32.f32 %0, %1;" : "=r"(r) : "f"(f));
    return __uint_as_float(r);
}

#define MMA_TF32(c, A0, A1, A2, A3, B0, B1) \
    asm volatile("mma.sync.aligned.m16n8k8.row.col.f32.tf32.tf32.f32 " \
        "{%0,%1,%2,%3}, {%4,%5,%6,%7}, {%8,%9}, {%0,%1,%2,%3};" \
        : "+f"((c)[0]), "+f"((c)[1]), "+f"((c)[2]), "+f"((c)[3]) \
        : "r"(__float_as_uint(A0)), "r"(__float_as_uint(A1)), \
          "r"(__float_as_uint(A2)), "r"(__float_as_uint(A3)), \
          "r"(__float_as_uint(B0)), "r"(__float_as_uint(B1)))

#define CP16(dst_u32, src_gptr) \
    asm volatile("cp.async.cg.shared.global [%0], [%1], 16;" \
        :: "r"(dst_u32), "l"(src_gptr) : "memory")
#define CP_COMMIT() asm volatile("cp.async.commit_group;" ::: "memory")
#define CP_WAIT(n)  asm volatile("cp.async.wait_group %0;" :: "n"(n) : "memory")

__device__ __forceinline__ uint32_t smem_u32(const void* p) {
    uint32_t a;
    asm("{ .reg .u64 t; cvta.to.shared.u64 t, %1; cvt.u32.u64 %0, t; }" : "=r"(a) : "l"(p));
    return a;
}

// ============================ GEMM config ==================================
#define BM     128
#define BN     128
#define BK     16
#define NCH    (KDIM / BK)            // 32
#define STAGES 4
#define SST    16                     // smem row stride (floats) — conflict-free
#define STAGEF ((BM + BN) * SST)      // 4096 floats = 16KB per stage
#define DSMEM_BYTES (STAGES * STAGEF * 4)   // 65536 B
#define NTHREADS 128                  // 4 warps, each 64x64 output tile

__device__ __forceinline__ float arc_apply(float cosv, bool istgt) {
    float o = cosv;
    if (istgt) {
        float sine = sqrtf(fmaxf(0.0f, 1.0f - cosv * cosv));
        float phi = cosv * COSM_F - sine * SINM_F;
        o = (cosv > TH_F) ? phi : (cosv - MMV_F);
    }
    return o * SCALE_F;
}

// ============================ prep kernel ==================================
// k-permutation within each 16-float group: element p -> pos (p&3)*4 + (p>>2)
__global__ void __launch_bounds__(128) prep_kernel(
    const float* __restrict__ X, const float* __restrict__ W,
    const int* __restrict__ L)
{
    const int b = blockIdx.x;
    const int t = threadIdx.x;

    if (b < BATCH_N + CLSP) {
        const bool isX = (b < BATCH_N);
        const int row = isX ? b : (b - BATCH_N);
        const float* src = isX ? (X + (size_t)row * KDIM)
                               : (W + (size_t)row * KDIM);
        float* dst = isX ? (g_Xr + (size_t)row * KDIM)
                         : (g_Wr + (size_t)row * KDIM);
        const bool valid = isX || (row < CLS);

        float4 v = make_float4(0.f, 0.f, 0.f, 0.f);
        if (valid) v = *(const float4*)(src + t * 4);
        float ss = v.x * v.x + v.y * v.y + v.z * v.z + v.w * v.w;

        float* gdst = dst + (t >> 2) * 16 + (t & 3);
        gdst[0]  = f2tf32(v.x);
        gdst[4]  = f2tf32(v.y);
        gdst[8]  = f2tf32(v.z);
        gdst[12] = f2tf32(v.w);

        #pragma unroll
        for (int o = 16; o; o >>= 1) ss += __shfl_down_sync(0xffffffffu, ss, o);
        __shared__ float ws[4];
        if ((t & 31) == 0) ws[t >> 5] = ss;
        __syncthreads();
        if (t == 0) {
            float tot = ws[0] + ws[1] + ws[2] + ws[3];
            float inv = valid ? (1.0f / fmaxf(sqrtf(tot), 1e-12f)) : 1.0f;
            if (isX) g_invx[row] = inv; else g_invw[row] = inv;
        }
    } else {
        int nz = 0;
        for (int i = t; i < 2048; i += 128)
            if (L[2 * i + 1] != 0) nz = 1;
        int any = __syncthreads_or(nz);
        const int is64 = any ? 0 : 1;
        for (int i = t; i < BATCH_N; i += 128) {
            g_label[i] = is64 ? L[2 * i] : L[i];
            g_rowsum[i] = 0.0f;
        }
    }
}

// ============================ main GEMM + ArcFace + loss ===================
extern __shared__ float smf[];

__device__ __forceinline__ void compute_chunk(
    const float* __restrict__ sb, int aoff, int boff,
    float acc[4][8][4])
{
    const float* Ab = sb + aoff;
    const float* Bb = sb + boff;
    float4 bq[8];
    #pragma unroll
    for (int k = 0; k < 8; ++k)
        bq[k] = *(const float4*)(Bb + 8 * k * SST);
    #pragma unroll
    for (int i = 0; i < 4; ++i) {
        float4 alo = *(const float4*)(Ab + (i * 16)     * SST);
        float4 ahi = *(const float4*)(Ab + (i * 16 + 8) * SST);
        #pragma unroll
        for (int j = 0; j < 8; ++j) {
            MMA_TF32(acc[i][j], alo.x, ahi.x, alo.y, ahi.y, bq[j].x, bq[j].y);
            MMA_TF32(acc[i][j], alo.z, ahi.z, alo.w, ahi.w, bq[j].z, bq[j].w);
        }
    }
}

__global__ void __launch_bounds__(NTHREADS, 2)
gemm_arcface_kernel(float* __restrict__ out, int do_loss)
{
    const int tid  = threadIdx.x;
    const int lane = tid & 31;
    const int wid  = tid >> 5;          // 0..3
    const int g    = lane >> 2;
    const int tm   = lane & 3;
    const int wm   = wid & 1;           // warp M index (0..1), 64 rows
    const int wn   = wid >> 1;          // warp N index (0..1), 64 cols
    const int rowBase = blockIdx.x * BM;
    const int colBase = blockIdx.y * BN;

    const uint32_t sbase = smem_u32(smf);

    // fragment smem offsets (floats), loop-invariant
    const int aoff = (wm * 64 + g) * SST + 4 * tm;
    const int boff = (BM + wn * 64 + g) * SST + 4 * tm;

    // cp.async mapping: quad covers row r0c (+32k), 128 threads -> 32 rows/quad-set
    const int r0c = tid >> 2, lc = tid & 3;
    const float* xsA = g_Xr + (size_t)(rowBase + r0c) * KDIM + lc * 4;
    const float* xsB = g_Wr + (size_t)(colBase + r0c) * KDIM + lc * 4;
    const uint32_t dA = sbase + (r0c * SST + lc * 4) * 4;
    const uint32_t dB = sbase + ((BM + r0c) * SST + lc * 4) * 4;

    float acc[4][8][4];
    #pragma unroll
    for (int i = 0; i < 4; ++i)
        #pragma unroll
        for (int j = 0; j < 8; ++j)
            #pragma unroll
            for (int q = 0; q < 4; ++q) acc[i][j][q] = 0.f;

    // prologue: stages 0..2 = chunks 0..2  (8 CP16 per thread per chunk)
    #pragma unroll
    for (int s = 0; s < STAGES - 1; ++s) {
        const uint32_t so = (uint32_t)(s * STAGEF * 4);
        const int ko = s * BK;
        #pragma unroll
        for (int k = 0; k < 4; ++k) {
            CP16(dA + so + k * 32 * SST * 4, xsA + (size_t)k * 32 * KDIM + ko);
            CP16(dB + so + k * 32 * SST * 4, xsB + (size_t)k * 32 * KDIM + ko);
        }
        CP_COMMIT();
    }

    // main loop: 7 blocks of 4 fully-unrolled chunks (computes chunks 0..27)
    #pragma unroll 1
    for (int cb = 0; cb < NCH / STAGES - 1; ++cb) {
        #pragma unroll
        for (int s = 0; s < STAGES; ++s) {
            CP_WAIT(2);
            __syncthreads();
            const uint32_t so = (uint32_t)((((s + 3) & 3) * STAGEF) * 4);
            const int ko = (s + 3) * BK;        // + cb*64 via pointer advance
            #pragma unroll
            for (int k = 0; k < 4; ++k) {
                CP16(dA + so + k * 32 * SST * 4, xsA + (size_t)k * 32 * KDIM + ko);
                CP16(dB + so + k * 32 * SST * 4, xsB + (size_t)k * 32 * KDIM + ko);
            }
            CP_COMMIT();
            compute_chunk(smf + s * STAGEF, aoff, boff, acc);
        }
        xsA += STAGES * BK;
        xsB += STAGES * BK;
    }
    // tail: chunks 28..31 (prefetch chunk 31 in first slot)
    CP_WAIT(2);
    __syncthreads();
    {
        const uint32_t so = (uint32_t)(3 * STAGEF * 4);
        const int ko = 3 * BK;
        #pragma unroll
        for (int k = 0; k < 4; ++k) {
            CP16(dA + so + k * 32 * SST * 4, xsA + (size_t)k * 32 * KDIM + ko);
            CP16(dB + so + k * 32 * SST * 4, xsB + (size_t)k * 32 * KDIM + ko);
        }
        CP_COMMIT();
    }
    compute_chunk(smf + 0 * STAGEF, aoff, boff, acc);
    CP_WAIT(2);
    __syncthreads();
    compute_chunk(smf + 1 * STAGEF, aoff, boff, acc);
    CP_WAIT(1);
    __syncthreads();
    compute_chunk(smf + 2 * STAGEF, aoff, boff, acc);
    CP_WAIT(0);
    __syncthreads();
    compute_chunk(smf + 3 * STAGEF, aoff, boff, acc);

    // ---- epilogue: normalize, ArcFace margin, scale, store, fused LSE ----
    __syncthreads();
    float* rowacc = smf;               // reuse stage smem: 128 floats
    if (tid < BM) rowacc[tid] = 0.f;
    __syncthreads();

    const int wrowb = rowBase + wm * 64;
    const int wcolb = colBase + wn * 64;
    #pragma unroll
    for (int i = 0; i < 4; ++i) {
        const int r0 = wrowb + i * 16 + g;
        const int r1 = r0 + 8;
        const float ix0 = g_invx[r0], ix1 = g_invx[r1];
        const int lab0 = g_label[r0], lab1 = g_label[r1];
        float* o0 = out + (size_t)r0 * CLS;
        float* o1 = out + (size_t)r1 * CLS;
        float es0 = 0.f, es1 = 0.f;
        #pragma unroll
        for (int j = 0; j < 8; ++j) {
            const int cc = wcolb + j * 8 + 2 * tm;
            if (cc < CLS) {   // cc even, CLS even => cc+1 < CLS too
                const float iw0 = g_invw[cc], iw1 = g_invw[cc + 1];
                const bool t00 = (cc == lab0), t01 = (cc + 1 == lab0);
                const bool t10 = (cc == lab1), t11 = (cc + 1 == lab1);
                float2 v0, v1;
                v0.x = arc_apply(acc[i][j][0] * ix0 * iw0, t00);
                v0.y = arc_apply(acc[i][j][1] * ix0 * iw1, t01);
                v1.x = arc_apply(acc[i][j][2] * ix1 * iw0, t10);
                v1.y = arc_apply(acc[i][j][3] * ix1 * iw1, t11);
                *(float2*)(o0 + cc) = v0;
                *(float2*)(o1 + cc) = v1;
                es0 += __expf(v0.x - LMAX_F) + __expf(v0.y - LMAX_F);
                es1 += __expf(v1.x - LMAX_F) + __expf(v1.y - LMAX_F);
                if (t00) g_tgt[r0] = v0.x;
                if (t01) g_tgt[r0] = v0.y;
                if (t10) g_tgt[r1] = v1.x;
                if (t11) g_tgt[r1] = v1.y;
            }
        }
        es0 += __shfl_xor_sync(0xffffffffu, es0, 1);
        es0 += __shfl_xor_sync(0xffffffffu, es0, 2);
        es1 += __shfl_xor_sync(0xffffffffu, es1, 1);
        es1 += __shfl_xor_sync(0xffffffffu, es1, 2);
        if (tm == 0) {
            atomicAdd(&rowacc[wm * 64 + i * 16 + g],     es0);
            atomicAdd(&rowacc[wm * 64 + i * 16 + g + 8], es1);
        }
    }
    __syncthreads();
    if (tid < BM) atomicAdd(&g_rowsum[rowBase + tid], rowacc[tid]);

    // ---- completion-counter: last CTA computes the CE loss ----
    __shared__ unsigned int s_last;
    __syncthreads();
    if (tid == 0) {
        __threadfence();
        unsigned int total = gridDim.x * gridDim.y;
        unsigned int old = atomicAdd(&g_ctr, 1u);
        s_last = (old == total - 1u) ? 1u : 0u;
    }
    __syncthreads();
    if (s_last) {
        if (tid == 0) g_ctr = 0;
        if (do_loss) {
            __threadfence();
            float s = 0.f;
            for (int i = tid; i < BATCH_N; i += NTHREADS)
                s += (LMAX_F + logf(g_rowsum[i])) - g_tgt[i];
            #pragma unroll
            for (int o = 16; o; o >>= 1) s += __shfl_down_sync(0xffffffffu, s, o);
            float* lsm = smf + 256;
            if (lane == 0) lsm[wid] = s;
            __syncthreads();
            if (tid == 0) {
                float t = 0.f;
                #pragma unroll
                for (int w = 0; w < NTHREADS / 32; ++w) t += lsm[w];
                out[(size_t)BATCH_N * CLS] = t * (1.0f / (float)BATCH_N);
            }
        }
    }
}

// ============================ launcher =====================================
extern "C" void kernel_launch(void* const* d_in, const int* in_sizes, int n_in,
                              void* d_out, int out_size) {
    const float* X = nullptr;
    const float* W = nullptr;
    const int*   L = nullptr;
    for (int i = 0; i < n_in; ++i) {
        if (in_sizes[i] == BATCH_N * KDIM)      X = (const float*)d_in[i];
        else if (in_sizes[i] == CLS * KDIM)     W = (const float*)d_in[i];
        else if (in_sizes[i] == BATCH_N)        L = (const int*)d_in[i];
    }
    float* out = (float*)d_out;
    const int do_loss = ((long long)out_size > (long long)BATCH_N * CLS) ? 1 : 0;

    cudaFuncSetAttribute(gemm_arcface_kernel,
                         cudaFuncAttributeMaxDynamicSharedMemorySize, DSMEM_BYTES);

    // exactly 2 launches per call => ncu -s 5 lands on GEMM
    prep_kernel<<<BATCH_N + CLSP + 1, 128>>>(X, W, L);

    dim3 grid(BATCH_N / BM, CLSP / BN);    // x fast-varying: share W tile in L2
    gemm_arcface_kernel<<<grid, NTHREADS, DSMEM_BYTES>>>(out, do_loss);
}

// round 11
// speedup vs baseline: 1.1715x; 1.0174x over previous
#include <cuda_runtime.h>
#include <cstdint>
#include <cstddef>

// ============================ problem constants ============================
#define BATCH_N   4096
#define KDIM      512
#define CLS       50000
#define CLSP      50048              // padded to 391*128
#define SCALE_F   30.0f
#define LMAX_F    30.0f
#define COSM_F    0.8775825618903728f
#define SINM_F    0.479425538604203f
#define TH_F     (-0.8775825618903728f)
#define MMV_F     0.23971276930210156f

// ============================ device scratch ===============================
__device__ float g_Xr[BATCH_N * KDIM];   // tf32-rounded, k-permuted X
__device__ float g_Wr[CLSP * KDIM];      // tf32-rounded, k-permuted W (padded)
__device__ float g_invx[BATCH_N];
__device__ float g_invw[CLSP];
__device__ int   g_label[BATCH_N];
__device__ float g_rowsum[BATCH_N];      // sum of exp(logit - 30) per row
__device__ float g_tgt[BATCH_N];         // target-class logit per row
__device__ unsigned int g_ctr = 0;       // CTA completion counter

// ============================ helpers ======================================
__device__ __forceinline__ float f2tf32(float f) {
    uint32_t r; asm("cvt.rna.tf32.f32 %0, %1;" : "=r"(r) : "f"(f));
    return __uint_as_float(r);
}

#define MMA_TF32(c, A0, A1, A2, A3, B0, B1) \
    asm volatile("mma.sync.aligned.m16n8k8.row.col.f32.tf32.tf32.f32 " \
        "{%0,%1,%2,%3}, {%4,%5,%6,%7}, {%8,%9}, {%0,%1,%2,%3};" \
        : "+f"((c)[0]), "+f"((c)[1]), "+f"((c)[2]), "+f"((c)[3]) \
        : "r"(__float_as_uint(A0)), "r"(__float_as_uint(A1)), \
          "r"(__float_as_uint(A2)), "r"(__float_as_uint(A3)), \
          "r"(__float_as_uint(B0)), "r"(__float_as_uint(B1)))

#define CP16(dst_u32, src_gptr) \
    asm volatile("cp.async.cg.shared.global [%0], [%1], 16;" \
        :: "r"(dst_u32), "l"(src_gptr) : "memory")
#define CP_COMMIT() asm volatile("cp.async.commit_group;" ::: "memory")
#define CP_WAIT(n)  asm volatile("cp.async.wait_group %0;" :: "n"(n) : "memory")

__device__ __forceinline__ uint32_t smem_u32(const void* p) {
    uint32_t a;
    asm("{ .reg .u64 t; cvta.to.shared.u64 t, %1; cvt.u32.u64 %0, t; }" : "=r"(a) : "l"(p));
    return a;
}

// ============================ GEMM config ==================================
#define BM     128
#define BN     128
#define BK     16
#define NCH    (KDIM / BK)            // 32
#define STAGES 4
#define SST    16                     // smem row stride (floats) — conflict-free
#define STAGEF ((BM + BN) * SST)      // 4096 floats = 16KB per stage
#define DSMEM_BYTES (STAGES * STAGEF * 4)   // 65536 B
#define NTHREADS 256                  // 8 warps, each 64x32 output tile

__device__ __forceinline__ float arc_apply(float cosv, bool istgt) {
    float o = cosv;
    if (istgt) {
        float sine = sqrtf(fmaxf(0.0f, 1.0f - cosv * cosv));
        float phi = cosv * COSM_F - sine * SINM_F;
        o = (cosv > TH_F) ? phi : (cosv - MMV_F);
    }
    return o * SCALE_F;
}

// ============================ prep kernel ==================================
// k-permutation within each 16-float group: element p -> pos (p&3)*4 + (p>>2)
__global__ void __launch_bounds__(128) prep_kernel(
    const float* __restrict__ X, const float* __restrict__ W,
    const int* __restrict__ L)
{
    const int b = blockIdx.x;
    const int t = threadIdx.x;

    if (b < BATCH_N + CLSP) {
        const bool isX = (b < BATCH_N);
        const int row = isX ? b : (b - BATCH_N);
        const float* src = isX ? (X + (size_t)row * KDIM)
                               : (W + (size_t)row * KDIM);
        float* dst = isX ? (g_Xr + (size_t)row * KDIM)
                         : (g_Wr + (size_t)row * KDIM);
        const bool valid = isX || (row < CLS);

        float4 v = make_float4(0.f, 0.f, 0.f, 0.f);
        if (valid) v = *(const float4*)(src + t * 4);
        float ss = v.x * v.x + v.y * v.y + v.z * v.z + v.w * v.w;

        float* gdst = dst + (t >> 2) * 16 + (t & 3);
        gdst[0]  = f2tf32(v.x);
        gdst[4]  = f2tf32(v.y);
        gdst[8]  = f2tf32(v.z);
        gdst[12] = f2tf32(v.w);

        #pragma unroll
        for (int o = 16; o; o >>= 1) ss += __shfl_down_sync(0xffffffffu, ss, o);
        __shared__ float ws[4];
        if ((t & 31) == 0) ws[t >> 5] = ss;
        __syncthreads();
        if (t == 0) {
            float tot = ws[0] + ws[1] + ws[2] + ws[3];
            float inv = valid ? (1.0f / fmaxf(sqrtf(tot), 1e-12f)) : 1.0f;
            if (isX) g_invx[row] = inv; else g_invw[row] = inv;
        }
    } else {
        int nz = 0;
        for (int i = t; i < 2048; i += 128)
            if (L[2 * i + 1] != 0) nz = 1;
        int any = __syncthreads_or(nz);
        const int is64 = any ? 0 : 1;
        for (int i = t; i < BATCH_N; i += 128) {
            g_label[i] = is64 ? L[2 * i] : L[i];
            g_rowsum[i] = 0.0f;
        }
    }
}

// ============================ main GEMM + ArcFace + loss ===================
extern __shared__ float smf[];

__device__ __forceinline__ void compute_chunk(
    const float* __restrict__ sb, int aoff, int boff,
    float acc[4][4][4])
{
    const float* Ab = sb + aoff;
    const float* Bb = sb + boff;
    float4 bq0 = *(const float4*)(Bb);
    float4 bq1 = *(const float4*)(Bb + 8  * SST);
    float4 bq2 = *(const float4*)(Bb + 16 * SST);
    float4 bq3 = *(const float4*)(Bb + 24 * SST);
    #pragma unroll
    for (int i = 0; i < 4; ++i) {
        float4 alo = *(const float4*)(Ab + (i * 16)     * SST);
        float4 ahi = *(const float4*)(Ab + (i * 16 + 8) * SST);
        MMA_TF32(acc[i][0], alo.x, ahi.x, alo.y, ahi.y, bq0.x, bq0.y);
        MMA_TF32(acc[i][1], alo.x, ahi.x, alo.y, ahi.y, bq1.x, bq1.y);
        MMA_TF32(acc[i][2], alo.x, ahi.x, alo.y, ahi.y, bq2.x, bq2.y);
        MMA_TF32(acc[i][3], alo.x, ahi.x, alo.y, ahi.y, bq3.x, bq3.y);
        MMA_TF32(acc[i][0], alo.z, ahi.z, alo.w, ahi.w, bq0.z, bq0.w);
        MMA_TF32(acc[i][1], alo.z, ahi.z, alo.w, ahi.w, bq1.z, bq1.w);
        MMA_TF32(acc[i][2], alo.z, ahi.z, alo.w, ahi.w, bq2.z, bq2.w);
        MMA_TF32(acc[i][3], alo.z, ahi.z, alo.w, ahi.w, bq3.z, bq3.w);
    }
}

__global__ void __launch_bounds__(NTHREADS, 2)
gemm_arcface_kernel(float* __restrict__ out, int do_loss)
{
    const int tid  = threadIdx.x;
    const int lane = tid & 31;
    const int wid  = tid >> 5;          // 0..7
    const int g    = lane >> 2;
    const int tm   = lane & 3;
    const int wm   = wid & 1;           // warp M index (0..1), 64 rows
    const int wn   = wid >> 1;          // warp N index (0..3), 32 cols
    const int rowBase = blockIdx.x * BM;
    const int colBase = blockIdx.y * BN;

    const uint32_t sbase = smem_u32(smf);

    // fragment smem offsets (floats), loop-invariant
    const int aoff = (wm * 64 + g) * SST + 4 * tm;
    const int boff = (BM + wn * 32 + g) * SST + 4 * tm;

    // cp.async mapping: thread covers rows (lr, lr+64) of both A and B
    const int r0c = tid >> 2, lc = tid & 3;
    const int r1c = r0c + 64;
    const float* xs0 = g_Xr + (size_t)(rowBase + r0c) * KDIM + lc * 4;
    const float* xs1 = g_Xr + (size_t)(rowBase + r1c) * KDIM + lc * 4;
    const float* ws0 = g_Wr + (size_t)(colBase + r0c) * KDIM + lc * 4;
    const float* ws1 = g_Wr + (size_t)(colBase + r1c) * KDIM + lc * 4;
    const uint32_t dA0 = sbase + (r0c * SST + lc * 4) * 4;
    const uint32_t dA1 = sbase + (r1c * SST + lc * 4) * 4;
    const uint32_t dB0 = sbase + ((BM + r0c) * SST + lc * 4) * 4;
    const uint32_t dB1 = sbase + ((BM + r1c) * SST + lc * 4) * 4;

    float acc[4][4][4];
    #pragma unroll
    for (int i = 0; i < 4; ++i)
        #pragma unroll
        for (int j = 0; j < 4; ++j)
            #pragma unroll
            for (int q = 0; q < 4; ++q) acc[i][j][q] = 0.f;

    // prologue: stages 0..2 = chunks 0..2
    #pragma unroll
    for (int s = 0; s < STAGES - 1; ++s) {
        const uint32_t so = (uint32_t)(s * STAGEF * 4);
        const int ko = s * BK;
        CP16(dA0 + so, xs0 + ko);
        CP16(dA1 + so, xs1 + ko);
        CP16(dB0 + so, ws0 + ko);
        CP16(dB1 + so, ws1 + ko);
        CP_COMMIT();
    }

    // main loop: 7 blocks of 4 fully-unrolled chunks (chunks 0..27)
    // stage offsets are compile-time constants; global ptrs advance 64/block
    #pragma unroll 1
    for (int cb = 0; cb < NCH / STAGES - 1; ++cb) {
        #pragma unroll
        for (int s = 0; s < STAGES; ++s) {
            CP_WAIT(2);
            __syncthreads();
            const uint32_t so = (uint32_t)((((s + 3) & 3) * STAGEF) * 4);
            const int ko = (s + 3) * BK;        // + cb*64 via pointer advance
            CP16(dA0 + so, xs0 + ko);
            CP16(dA1 + so, xs1 + ko);
            CP16(dB0 + so, ws0 + ko);
            CP16(dB1 + so, ws1 + ko);
            CP_COMMIT();
            compute_chunk(smf + s * STAGEF, aoff, boff, acc);
        }
        xs0 += STAGES * BK; xs1 += STAGES * BK;
        ws0 += STAGES * BK; ws1 += STAGES * BK;
    }
    // tail: chunks 28..31 (prefetch chunk 31 in first slot)
    CP_WAIT(2);
    __syncthreads();
    {
        const uint32_t so = (uint32_t)(3 * STAGEF * 4);
        const int ko = 3 * BK;
        CP16(dA0 + so, xs0 + ko);
        CP16(dA1 + so, xs1 + ko);
        CP16(dB0 + so, ws0 + ko);
        CP16(dB1 + so, ws1 + ko);
        CP_COMMIT();
    }
    compute_chunk(smf + 0 * STAGEF, aoff, boff, acc);
    CP_WAIT(2);
    __syncthreads();
    compute_chunk(smf + 1 * STAGEF, aoff, boff, acc);
    CP_WAIT(1);
    __syncthreads();
    compute_chunk(smf + 2 * STAGEF, aoff, boff, acc);
    CP_WAIT(0);
    __syncthreads();
    compute_chunk(smf + 3 * STAGEF, aoff, boff, acc);

    // ---- epilogue: normalize, ArcFace margin, scale, store, fused LSE ----
    __syncthreads();
    float* rowacc = smf;               // reuse stage smem: 128 floats
    if (tid < BM) rowacc[tid] = 0.f;
    __syncthreads();

    const int wrowb = rowBase + wm * 64;
    const int wcolb = colBase + wn * 32;
    #pragma unroll
    for (int i = 0; i < 4; ++i) {
        const int r0 = wrowb + i * 16 + g;
        const int r1 = r0 + 8;
        const float ix0 = g_invx[r0], ix1 = g_invx[r1];
        const int lab0 = g_label[r0], lab1 = g_label[r1];
        float* o0 = out + (size_t)r0 * CLS;
        float* o1 = out + (size_t)r1 * CLS;
        float es0 = 0.f, es1 = 0.f;
        #pragma unroll
        for (int j = 0; j < 4; ++j) {
            const int cc = wcolb + j * 8 + 2 * tm;
            if (cc < CLS) {   // cc even, CLS even => cc+1 < CLS too
                const float iw0 = g_invw[cc], iw1 = g_invw[cc + 1];
                const bool t00 = (cc == lab0), t01 = (cc + 1 == lab0);
                const bool t10 = (cc == lab1), t11 = (cc + 1 == lab1);
                float2 v0, v1;
                v0.x = arc_apply(acc[i][j][0] * ix0 * iw0, t00);
                v0.y = arc_apply(acc[i][j][1] * ix0 * iw1, t01);
                v1.x = arc_apply(acc[i][j][2] * ix1 * iw0, t10);
                v1.y = arc_apply(acc[i][j][3] * ix1 * iw1, t11);
                *(float2*)(o0 + cc) = v0;
                *(float2*)(o1 + cc) = v1;
                es0 += __expf(v0.x - LMAX_F) + __expf(v0.y - LMAX_F);
                es1 += __expf(v1.x - LMAX_F) + __expf(v1.y - LMAX_F);
                if (t00) g_tgt[r0] = v0.x;
                if (t01) g_tgt[r0] = v0.y;
                if (t10) g_tgt[r1] = v1.x;
                if (t11) g_tgt[r1] = v1.y;
            }
        }
        es0 += __shfl_xor_sync(0xffffffffu, es0, 1);
        es0 += __shfl_xor_sync(0xffffffffu, es0, 2);
        es1 += __shfl_xor_sync(0xffffffffu, es1, 1);
        es1 += __shfl_xor_sync(0xffffffffu, es1, 2);
        if (tm == 0) {
            atomicAdd(&rowacc[wm * 64 + i * 16 + g],     es0);
            atomicAdd(&rowacc[wm * 64 + i * 16 + g + 8], es1);
        }
    }
    __syncthreads();
    if (tid < BM) atomicAdd(&g_rowsum[rowBase + tid], rowacc[tid]);

    // ---- completion-counter: last CTA computes the CE loss ----
    __shared__ unsigned int s_last;
    __syncthreads();
    if (tid == 0) {
        __threadfence();
        unsigned int total = gridDim.x * gridDim.y;
        unsigned int old = atomicAdd(&g_ctr, 1u);
        s_last = (old == total - 1u) ? 1u : 0u;
    }
    __syncthreads();
    if (s_last) {
        if (tid == 0) g_ctr = 0;
        if (do_loss) {
            __threadfence();
            float s = 0.f;
            for (int i = tid; i < BATCH_N; i += NTHREADS)
                s += (LMAX_F + logf(g_rowsum[i])) - g_tgt[i];
            #pragma unroll
            for (int o = 16; o; o >>= 1) s += __shfl_down_sync(0xffffffffu, s, o);
            float* lsm = smf + 256;
            if (lane == 0) lsm[wid] = s;
            __syncthreads();
            if (tid == 0) {
                float t = 0.f;
                #pragma unroll
                for (int w = 0; w < NTHREADS / 32; ++w) t += lsm[w];
                out[(size_t)BATCH_N * CLS] = t * (1.0f / (float)BATCH_N);
            }
        }
    }
}

// ============================ launcher =====================================
extern "C" void kernel_launch(void* const* d_in, const int* in_sizes, int n_in,
                              void* d_out, int out_size) {
    const float* X = nullptr;
    const float* W = nullptr;
    const int*   L = nullptr;
    for (int i = 0; i < n_in; ++i) {
        if (in_sizes[i] == BATCH_N * KDIM)      X = (const float*)d_in[i];
        else if (in_sizes[i] == CLS * KDIM)     W = (const float*)d_in[i];
        else if (in_sizes[i] == BATCH_N)        L = (const int*)d_in[i];
    }
    float* out = (float*)d_out;
    const int do_loss = ((long long)out_size > (long long)BATCH_N * CLS) ? 1 : 0;

    cudaFuncSetAttribute(gemm_arcface_kernel,
                         cudaFuncAttributeMaxDynamicSharedMemorySize, DSMEM_BYTES);

    // exactly 2 launches per call => ncu -s 5 lands on GEMM
    prep_kernel<<<BATCH_N + CLSP + 1, 128>>>(X, W, L);

    dim3 grid(BATCH_N / BM, CLSP / BN);    // x fast-varying: share W tile in L2
    gemm_arcface_kernel<<<grid, NTHREADS, DSMEM_BYTES>>>(out, do_loss);
}

// round 12
// speedup vs baseline: 1.4757x; 1.2597x over previous
#include <cuda_runtime.h>
#include <cstdint>
#include <cstddef>

// ============================ problem constants ============================
#define BATCH_N   4096
#define KDIM      512
#define CLS       50000
#define CLSP      50048              // padded to 391*128
#define SCALE_F   30.0f
#define LMAX_F    30.0f
#define COSM_F    0.8775825618903728f
#define SINM_F    0.479425538604203f
#define TH_F     (-0.8775825618903728f)
#define MMV_F     0.23971276930210156f

// ============================ device scratch ===============================
__device__ float g_Xr[BATCH_N * KDIM];   // tf32-rounded, FRAGMENT-MAJOR X
__device__ float g_Wr[CLSP * KDIM];      // tf32-rounded, k-permuted W (padded)
__device__ float g_invx[BATCH_N];
__device__ float g_invw[CLSP];
__device__ int   g_label[BATCH_N];
__device__ float g_rowsum[BATCH_N];      // sum of exp(logit - 30) per row
__device__ float g_tgt[BATCH_N];         // target-class logit per row
__device__ unsigned int g_ctr = 0;       // CTA completion counter

// ============================ helpers ======================================
__device__ __forceinline__ float f2tf32(float f) {
    uint32_t r; asm("cvt.rna.tf32.f32 %0, %1;" : "=r"(r) : "f"(f));
    return __uint_as_float(r);
}

#define MMA_TF32(c, A0, A1, A2, A3, B0, B1) \
    asm volatile("mma.sync.aligned.m16n8k8.row.col.f32.tf32.tf32.f32 " \
        "{%0,%1,%2,%3}, {%4,%5,%6,%7}, {%8,%9}, {%0,%1,%2,%3};" \
        : "+f"((c)[0]), "+f"((c)[1]), "+f"((c)[2]), "+f"((c)[3]) \
        : "r"(__float_as_uint(A0)), "r"(__float_as_uint(A1)), \
          "r"(__float_as_uint(A2)), "r"(__float_as_uint(A3)), \
          "r"(__float_as_uint(B0)), "r"(__float_as_uint(B1)))

#define CP16(dst_u32, src_gptr) \
    asm volatile("cp.async.cg.shared.global [%0], [%1], 16;" \
        :: "r"(dst_u32), "l"(src_gptr) : "memory")
#define CP_COMMIT() asm volatile("cp.async.commit_group;" ::: "memory")
#define CP_WAIT(n)  asm volatile("cp.async.wait_group %0;" :: "n"(n) : "memory")

__device__ __forceinline__ uint32_t smem_u32(const void* p) {
    uint32_t a;
    asm("{ .reg .u64 t; cvta.to.shared.u64 t, %1; cvt.u32.u64 %0, t; }" : "=r"(a) : "l"(p));
    return a;
}

// ============================ GEMM config ==================================
#define BM     128
#define BN     128
#define BK     16
#define NCH    (KDIM / BK)            // 32
#define STAGES 4
// A chunk: 2048 floats, fragment-major, contiguous 8KB
// B chunk: 128 rows x 16 floats (k-permuted), 8KB
#define ACH    2048
#define STAGEF (ACH + BN * 16)        // 4096 floats = 16KB per stage
#define DSMEM_BYTES (STAGES * STAGEF * 4)   // 65536 B
#define NTHREADS 256                  // 8 warps, each 64x32 output tile

__device__ __forceinline__ float arc_apply(float cosv, bool istgt) {
    float o = cosv;
    if (istgt) {
        float sine = sqrtf(fmaxf(0.0f, 1.0f - cosv * cosv));
        float phi = cosv * COSM_F - sine * SINM_F;
        o = (cosv > TH_F) ? phi : (cosv - MMV_F);
    }
    return o * SCALE_F;
}

// ============================ prep kernel ==================================
// X rows -> fragment-major layout:
//   g_Xr[(rowTile*32 + c)*2048 + ((s*8 + mb)*32 + lane)*4 + e]
//   rowTile=row>>7, mb=(row>>4)&7, g=row&7, h=(row>>3)&1,
//   c=k>>4, s=(k>>3)&1, tm=k&3, v=(k>>2)&1, lane=g*4+tm, e=h+2v
// W rows  -> k-permuted row-major (pos (k&3)*4 + (k>>2)), 16-float rows
__global__ void __launch_bounds__(128) prep_kernel(
    const float* __restrict__ X, const float* __restrict__ W,
    const int* __restrict__ L)
{
    const int b = blockIdx.x;
    const int t = threadIdx.x;

    if (b < BATCH_N) {
        // X row, fragment-major scatter
        const int row = b;
        const float* src = X + (size_t)row * KDIM;
        float4 v = *(const float4*)(src + t * 4);
        float ss = v.x * v.x + v.y * v.y + v.z * v.z + v.w * v.w;

        // thread t covers k = 4t..4t+3: c=t>>2, s=(t>>1)&1, vv=t&1, tm=d
        float* dst = g_Xr
            + ((size_t)(row >> 7) * 32 + (t >> 2)) * ACH
            + ((((t >> 1) & 1) * 8 + ((row >> 4) & 7)) * 32 + (row & 7) * 4) * 4
            + ((row >> 3) & 1) + 2 * (t & 1);
        dst[0]  = f2tf32(v.x);
        dst[4]  = f2tf32(v.y);
        dst[8]  = f2tf32(v.z);
        dst[12] = f2tf32(v.w);

        #pragma unroll
        for (int o = 16; o; o >>= 1) ss += __shfl_down_sync(0xffffffffu, ss, o);
        __shared__ float ws[4];
        if ((t & 31) == 0) ws[t >> 5] = ss;
        __syncthreads();
        if (t == 0)
            g_invx[row] = 1.0f / fmaxf(sqrtf(ws[0] + ws[1] + ws[2] + ws[3]), 1e-12f);
    } else if (b < BATCH_N + CLSP) {
        const int row = b - BATCH_N;
        const bool valid = (row < CLS);
        float4 v = make_float4(0.f, 0.f, 0.f, 0.f);
        if (valid) v = *(const float4*)(W + (size_t)row * KDIM + t * 4);
        float ss = v.x * v.x + v.y * v.y + v.z * v.z + v.w * v.w;

        float* gdst = g_Wr + (size_t)row * KDIM + (t >> 2) * 16 + (t & 3);
        gdst[0]  = f2tf32(v.x);
        gdst[4]  = f2tf32(v.y);
        gdst[8]  = f2tf32(v.z);
        gdst[12] = f2tf32(v.w);

        #pragma unroll
        for (int o = 16; o; o >>= 1) ss += __shfl_down_sync(0xffffffffu, ss, o);
        __shared__ float ws2[4];
        if ((t & 31) == 0) ws2[t >> 5] = ss;
        __syncthreads();
        if (t == 0) {
            float tot = ws2[0] + ws2[1] + ws2[2] + ws2[3];
            g_invw[row] = valid ? (1.0f / fmaxf(sqrtf(tot), 1e-12f)) : 1.0f;
        }
    } else {
        int nz = 0;
        for (int i = t; i < 2048; i += 128)
            if (L[2 * i + 1] != 0) nz = 1;
        int any = __syncthreads_or(nz);
        const int is64 = any ? 0 : 1;
        for (int i = t; i < BATCH_N; i += 128) {
            g_label[i] = is64 ? L[2 * i] : L[i];
            g_rowsum[i] = 0.0f;
        }
    }
}

// ============================ main GEMM + ArcFace + loss ===================
extern __shared__ float smf[];

// A fragment: one LDS.128 -> 4 consecutive regs, directly MMA-ready.
__device__ __forceinline__ void compute_chunk(
    const float* __restrict__ sb, int awoff, int boff,
    float acc[4][4][4])
{
    const float* Ab = sb + awoff;          // + s*1024 + i*128 below
    const float* Bb = sb + boff;
    float4 bq0 = *(const float4*)(Bb);
    float4 bq1 = *(const float4*)(Bb + 8  * 16);
    float4 bq2 = *(const float4*)(Bb + 16 * 16);
    float4 bq3 = *(const float4*)(Bb + 24 * 16);
    #pragma unroll
    for (int i = 0; i < 4; ++i) {
        float4 a0 = *(const float4*)(Ab + i * 128);          // k-step 0
        float4 a1 = *(const float4*)(Ab + 1024 + i * 128);   // k-step 1
        MMA_TF32(acc[i][0], a0.x, a0.y, a0.z, a0.w, bq0.x, bq0.y);
        MMA_TF32(acc[i][1], a0.x, a0.y, a0.z, a0.w, bq1.x, bq1.y);
        MMA_TF32(acc[i][2], a0.x, a0.y, a0.z, a0.w, bq2.x, bq2.y);
        MMA_TF32(acc[i][3], a0.x, a0.y, a0.z, a0.w, bq3.x, bq3.y);
        MMA_TF32(acc[i][0], a1.x, a1.y, a1.z, a1.w, bq0.z, bq0.w);
        MMA_TF32(acc[i][1], a1.x, a1.y, a1.z, a1.w, bq1.z, bq1.w);
        MMA_TF32(acc[i][2], a1.x, a1.y, a1.z, a1.w, bq2.z, bq2.w);
        MMA_TF32(acc[i][3], a1.x, a1.y, a1.z, a1.w, bq3.z, bq3.w);
    }
}

__global__ void __launch_bounds__(NTHREADS, 2)
gemm_arcface_kernel(float* __restrict__ out, int do_loss)
{
    const int tid  = threadIdx.x;
    const int lane = tid & 31;
    const int wid  = tid >> 5;          // 0..7
    const int g    = lane >> 2;
    const int tm   = lane & 3;
    const int wm   = wid & 1;           // warp M index (0..1), 64 rows
    const int wn   = wid >> 1;          // warp N index (0..3), 32 cols
    const int rowTile = blockIdx.x;     // 128-row tile index
    const int colBase = blockIdx.y * BN;

    const uint32_t sbase = smem_u32(smf);

    // fragment smem offsets (floats), loop-invariant
    const int awoff = wm * 4 * 128 + lane * 4;   // + i*128 + s*1024
    const int boff  = ACH + (wn * 32 + g) * 16 + 4 * tm;

    // cp.async A: contiguous 8KB chunk; thread copies 16B at tid*4 and 1024+tid*4
    const float* xsA = g_Xr + (size_t)rowTile * 32 * ACH + tid * 4;
    const uint32_t dAa = sbase + (tid * 4) * 4;
    const uint32_t dAb = sbase + (1024 + tid * 4) * 4;
    // cp.async B: rows r0c, r0c+64 of W (k-permuted 16-float rows per chunk)
    const int r0c = tid >> 2, lc = tid & 3;
    const int r1c = r0c + 64;
    const float* ws0 = g_Wr + (size_t)(colBase + r0c) * KDIM + lc * 4;
    const float* ws1 = g_Wr + (size_t)(colBase + r1c) * KDIM + lc * 4;
    const uint32_t dB0 = sbase + (ACH + r0c * 16 + lc * 4) * 4;
    const uint32_t dB1 = sbase + (ACH + r1c * 16 + lc * 4) * 4;

    float acc[4][4][4];
    #pragma unroll
    for (int i = 0; i < 4; ++i)
        #pragma unroll
        for (int j = 0; j < 4; ++j)
            #pragma unroll
            for (int q = 0; q < 4; ++q) acc[i][j][q] = 0.f;

    // prologue: stages 0..2 = chunks 0..2
    #pragma unroll
    for (int s = 0; s < STAGES - 1; ++s) {
        const uint32_t so = (uint32_t)(s * STAGEF * 4);
        CP16(dAa + so, xsA + s * ACH);
        CP16(dAb + so, xsA + s * ACH + 1024);
        CP16(dB0 + so, ws0 + s * BK);
        CP16(dB1 + so, ws1 + s * BK);
        CP_COMMIT();
    }

    // main loop: 7 blocks of 4 fully-unrolled chunks (chunks 0..27)
    #pragma unroll 1
    for (int cb = 0; cb < NCH / STAGES - 1; ++cb) {
        #pragma unroll
        for (int s = 0; s < STAGES; ++s) {
            CP_WAIT(2);
            __syncthreads();
            const uint32_t so = (uint32_t)((((s + 3) & 3) * STAGEF) * 4);
            CP16(dAa + so, xsA + (s + 3) * ACH);
            CP16(dAb + so, xsA + (s + 3) * ACH + 1024);
            CP16(dB0 + so, ws0 + (s + 3) * BK);
            CP16(dB1 + so, ws1 + (s + 3) * BK);
            CP_COMMIT();
            compute_chunk(smf + s * STAGEF, awoff, boff, acc);
        }
        xsA += STAGES * ACH;
        ws0 += STAGES * BK; ws1 += STAGES * BK;
    }
    // tail: chunks 28..31 (prefetch chunk 31 in first slot)
    CP_WAIT(2);
    __syncthreads();
    {
        const uint32_t so = (uint32_t)(3 * STAGEF * 4);
        CP16(dAa + so, xsA + 3 * ACH);
        CP16(dAb + so, xsA + 3 * ACH + 1024);
        CP16(dB0 + so, ws0 + 3 * BK);
        CP16(dB1 + so, ws1 + 3 * BK);
        CP_COMMIT();
    }
    compute_chunk(smf + 0 * STAGEF, awoff, boff, acc);
    CP_WAIT(2);
    __syncthreads();
    compute_chunk(smf + 1 * STAGEF, awoff, boff, acc);
    CP_WAIT(1);
    __syncthreads();
    compute_chunk(smf + 2 * STAGEF, awoff, boff, acc);
    CP_WAIT(0);
    __syncthreads();
    compute_chunk(smf + 3 * STAGEF, awoff, boff, acc);

    // ---- epilogue: normalize, ArcFace margin, scale, store, fused LSE ----
    __syncthreads();
    float* rowacc = smf;               // reuse stage smem: 128 floats
    if (tid < BM) rowacc[tid] = 0.f;
    __syncthreads();

    const int wrowb = rowTile * BM + wm * 64;
    const int wcolb = colBase + wn * 32;
    #pragma unroll
    for (int i = 0; i < 4; ++i) {
        const int r0 = wrowb + i * 16 + g;
        const int r1 = r0 + 8;
        const float ix0 = g_invx[r0], ix1 = g_invx[r1];
        const int lab0 = g_label[r0], lab1 = g_label[r1];
        float* o0 = out + (size_t)r0 * CLS;
        float* o1 = out + (size_t)r1 * CLS;
        float es0 = 0.f, es1 = 0.f;
        #pragma unroll
        for (int j = 0; j < 4; ++j) {
            const int cc = wcolb + j * 8 + 2 * tm;
            if (cc < CLS) {   // cc even, CLS even => cc+1 < CLS too
                const float iw0 = g_invw[cc], iw1 = g_invw[cc + 1];
                const bool t00 = (cc == lab0), t01 = (cc + 1 == lab0);
                const bool t10 = (cc == lab1), t11 = (cc + 1 == lab1);
                float2 v0, v1;
                v0.x = arc_apply(acc[i][j][0] * ix0 * iw0, t00);
                v0.y = arc_apply(acc[i][j][1] * ix0 * iw1, t01);
                v1.x = arc_apply(acc[i][j][2] * ix1 * iw0, t10);
                v1.y = arc_apply(acc[i][j][3] * ix1 * iw1, t11);
                *(float2*)(o0 + cc) = v0;
                *(float2*)(o1 + cc) = v1;
                es0 += __expf(v0.x - LMAX_F) + __expf(v0.y - LMAX_F);
                es1 += __expf(v1.x - LMAX_F) + __expf(v1.y - LMAX_F);
                if (t00) g_tgt[r0] = v0.x;
                if (t01) g_tgt[r0] = v0.y;
                if (t10) g_tgt[r1] = v1.x;
                if (t11) g_tgt[r1] = v1.y;
            }
        }
        es0 += __shfl_xor_sync(0xffffffffu, es0, 1);
        es0 += __shfl_xor_sync(0xffffffffu, es0, 2);
        es1 += __shfl_xor_sync(0xffffffffu, es1, 1);
        es1 += __shfl_xor_sync(0xffffffffu, es1, 2);
        if (tm == 0) {
            atomicAdd(&rowacc[wm * 64 + i * 16 + g],     es0);
            atomicAdd(&rowacc[wm * 64 + i * 16 + g + 8], es1);
        }
    }
    __syncthreads();
    if (tid < BM) atomicAdd(&g_rowsum[rowTile * BM + tid], rowacc[tid]);

    // ---- completion-counter: last CTA computes the CE loss ----
    __shared__ unsigned int s_last;
    __syncthreads();
    if (tid == 0) {
        __threadfence();
        unsigned int total = gridDim.x * gridDim.y;
        unsigned int old = atomicAdd(&g_ctr, 1u);
        s_last = (old == total - 1u) ? 1u : 0u;
    }
    __syncthreads();
    if (s_last) {
        if (tid == 0) g_ctr = 0;
        if (do_loss) {
            __threadfence();
            float s = 0.f;
            for (int i = tid; i < BATCH_N; i += NTHREADS)
                s += (LMAX_F + logf(g_rowsum[i])) - g_tgt[i];
            #pragma unroll
            for (int o = 16; o; o >>= 1) s += __shfl_down_sync(0xffffffffu, s, o);
            float* lsm = smf + 256;
            if (lane == 0) lsm[wid] = s;
            __syncthreads();
            if (tid == 0) {
                float t = 0.f;
                #pragma unroll
                for (int w = 0; w < NTHREADS / 32; ++w) t += lsm[w];
                out[(size_t)BATCH_N * CLS] = t * (1.0f / (float)BATCH_N);
            }
        }
    }
}

// ============================ launcher =====================================
extern "C" void kernel_launch(void* const* d_in, const int* in_sizes, int n_in,
                              void* d_out, int out_size) {
    const float* X = nullptr;
    const float* W = nullptr;
    const int*   L = nullptr;
    for (int i = 0; i < n_in; ++i) {
        if (in_sizes[i] == BATCH_N * KDIM)      X = (const float*)d_in[i];
        else if (in_sizes[i] == CLS * KDIM)     W = (const float*)d_in[i];
        else if (in_sizes[i] == BATCH_N)        L = (const int*)d_in[i];
    }
    float* out = (float*)d_out;
    const int do_loss = ((long long)out_size > (long long)BATCH_N * CLS) ? 1 : 0;

    cudaFuncSetAttribute(gemm_arcface_kernel,
                         cudaFuncAttributeMaxDynamicSharedMemorySize, DSMEM_BYTES);

    // exactly 2 launches per call => ncu -s 5 lands on GEMM
    prep_kernel<<<BATCH_N + CLSP + 1, 128>>>(X, W, L);

    dim3 grid(BATCH_N / BM, CLSP / BN);    // x fast-varying: share W tile in L2
    gemm_arcface_kernel<<<grid, NTHREADS, DSMEM_BYTES>>>(out, do_loss);
}